// round 3
// baseline (speedup 1.0000x reference)
#include <cuda_runtime.h>
#include <cuda_bf16.h>
#include <math.h>

#define NB 64
#define NP 24564
#define NM 16
#define NC 21

// ---------------- device scratch (no allocations allowed) ----------------
__device__ unsigned long long g_winner[NB * NM];   // packed (iou_bits<<32)|(~prior)
__device__ int    g_bt_idx[NB * NP];               // best truth per prior (after override)
__device__ float  g_bt_ov [NB * NP];               // best overlap per prior (after override)
__device__ float  g_mined [NB * NP];               // mined conf loss (0 at positives)
__device__ int    g_num_pos[NB];
__device__ double g_loss_l;
__device__ double g_loss_c;

// ---------------- kernel A: init ----------------
__global__ void k_init() {
    int i = blockIdx.x * blockDim.x + threadIdx.x;
    if (i < NB * NM) g_winner[i] = 0ull;
    if (i < NB) g_num_pos[i] = 0;
    if (i == 0) { g_loss_l = 0.0; g_loss_c = 0.0; }
}

// ---------------- kernel B: match (IoU, argmaxes) ----------------
__global__ void k_match(const float* __restrict__ priors,
                        const float* __restrict__ targets) {
    const int n   = blockIdx.y;
    const int tid = threadIdx.x;

    __shared__ float t_x1[NM], t_y1[NM], t_x2[NM], t_y2[NM], t_area[NM];
    __shared__ unsigned long long sh_key[NM];
    if (tid < NM) {
        const float* tp = targets + (size_t)(n * NM + tid) * 5;
        float x1 = tp[0], y1 = tp[1], x2 = tp[2], y2 = tp[3];
        t_x1[tid] = x1; t_y1[tid] = y1; t_x2[tid] = x2; t_y2[tid] = y2;
        t_area[tid] = (x2 - x1) * (y2 - y1);
        sh_key[tid] = 0ull;
    }
    __syncthreads();

    const int p = blockIdx.x * blockDim.x + tid;
    unsigned long long key[NM];
    if (p < NP) {
        float4 pr = ((const float4*)priors)[p];
        float px1 = pr.x - pr.z * 0.5f, py1 = pr.y - pr.w * 0.5f;
        float px2 = pr.x + pr.z * 0.5f, py2 = pr.y + pr.w * 0.5f;
        float pa  = (px2 - px1) * (py2 - py1);
        float best_ov = -1.0f; int best_t = 0;
#pragma unroll
        for (int t = 0; t < NM; t++) {
            float ix = fmaxf(fminf(px2, t_x2[t]) - fmaxf(px1, t_x1[t]), 0.0f);
            float iy = fmaxf(fminf(py2, t_y2[t]) - fmaxf(py1, t_y1[t]), 0.0f);
            float inter = ix * iy;
            float iou = inter / (pa + t_area[t] - inter);
            if (iou > best_ov) { best_ov = iou; best_t = t; }   // first-index tiebreak
            key[t] = ((unsigned long long)__float_as_uint(iou) << 32)
                   | (unsigned long long)(0xFFFFFFFFu - (unsigned)p); // lower p wins ties
        }
        g_bt_idx[n * NP + p] = best_t;
        g_bt_ov [n * NP + p] = best_ov;
    } else {
#pragma unroll
        for (int t = 0; t < NM; t++) key[t] = 0ull;
    }

#pragma unroll
    for (int t = 0; t < NM; t++) {
        unsigned long long v = key[t];
#pragma unroll
        for (int o = 16; o; o >>= 1) {
            unsigned long long u = __shfl_down_sync(0xFFFFFFFFu, v, o);
            v = (u > v) ? u : v;
        }
        if ((tid & 31) == 0 && v) atomicMax(&sh_key[t], v);
    }
    __syncthreads();
    if (tid < NM && sh_key[tid])
        atomicMax(&g_winner[n * NM + tid], sh_key[tid]);
}

// ---------------- kernel C: forced-match overrides (last truth wins) ----------------
__global__ void k_force() {
    int n = threadIdx.x;
    if (n >= NB) return;
    for (int t = 0; t < NM; t++) {                 // sequential: last write wins
        unsigned long long w = g_winner[n * NM + t];
        unsigned p = 0xFFFFFFFFu - (unsigned)(w & 0xFFFFFFFFull);
        g_bt_ov [n * NP + p] = 2.0f;
        g_bt_idx[n * NP + p] = t;
    }
}

__device__ __forceinline__ float sl1(float d) {
    float a = fabsf(d);
    return (a < 1.0f) ? 0.5f * d * d : a - 0.5f;
}

// ---------------- kernel D: LSE + gather + smooth-L1 + mined ----------------
__global__ void k_main(const float* __restrict__ loc,
                       const float* __restrict__ conf,
                       const float* __restrict__ priors,
                       const float* __restrict__ targets) {
    const int n   = blockIdx.y;
    const int tid = threadIdx.x;

    __shared__ float t_x1[NM], t_y1[NM], t_x2[NM], t_y2[NM], t_lab[NM];
    if (tid < NM) {
        const float* tp = targets + (size_t)(n * NM + tid) * 5;
        t_x1[tid] = tp[0]; t_y1[tid] = tp[1];
        t_x2[tid] = tp[2]; t_y2[tid] = tp[3];
        t_lab[tid] = tp[4];
    }
    __syncthreads();

    const int p = blockIdx.x * blockDim.x + tid;
    float local_ll = 0.0f, local_plc = 0.0f;
    int   local_np = 0;

    if (p < NP) {
        int   bt = g_bt_idx[n * NP + p];
        float ov = g_bt_ov [n * NP + p];
        int conf_t = (ov < 0.5f) ? 0 : ((int)t_lab[bt] + 1);
        bool pos = conf_t > 0;

        const float* row = conf + ((size_t)n * NP + (size_t)p) * NC;
        float vals[NC];
        float mx = -1e30f;
#pragma unroll
        for (int c = 0; c < NC; c++) { vals[c] = row[c]; mx = fmaxf(mx, vals[c]); }
        float s = 0.0f;
#pragma unroll
        for (int c = 0; c < NC; c++) s += __expf(vals[c] - mx);
        float lse = mx + __logf(s);
        float lc  = lse - vals[conf_t];

        g_mined[n * NP + p] = pos ? 0.0f : lc;

        if (pos) {
            local_np  = 1;
            local_plc = lc;
            float4 pr = ((const float4*)priors)[p];
            float mx1 = t_x1[bt], my1 = t_y1[bt], mx2 = t_x2[bt], my2 = t_y2[bt];
            float gx = ((mx1 + mx2) * 0.5f - pr.x) / (0.1f * pr.z);
            float gy = ((my1 + my2) * 0.5f - pr.y) / (0.1f * pr.w);
            float gw = logf((mx2 - mx1) / pr.z) / 0.2f;
            float gh = logf((my2 - my1) / pr.w) / 0.2f;
            const float* lp = loc + ((size_t)n * NP + (size_t)p) * 4;
            local_ll = sl1(lp[0] - gx) + sl1(lp[1] - gy)
                     + sl1(lp[2] - gw) + sl1(lp[3] - gh);
        }
    }

    // block reduce
#pragma unroll
    for (int o = 16; o; o >>= 1) {
        local_ll  += __shfl_down_sync(0xFFFFFFFFu, local_ll,  o);
        local_plc += __shfl_down_sync(0xFFFFFFFFu, local_plc, o);
        local_np  += __shfl_down_sync(0xFFFFFFFFu, local_np,  o);
    }
    __shared__ float s_ll, s_plc; __shared__ int s_np;
    if (tid == 0) { s_ll = 0.0f; s_plc = 0.0f; s_np = 0; }
    __syncthreads();
    if ((tid & 31) == 0) {
        if (local_ll  != 0.0f) atomicAdd(&s_ll,  local_ll);
        if (local_plc != 0.0f) atomicAdd(&s_plc, local_plc);
        if (local_np)          atomicAdd(&s_np,  local_np);
    }
    __syncthreads();
    if (tid == 0) {
        if (s_np)          atomicAdd(&g_num_pos[n], s_np);
        if (s_ll  != 0.0f) atomicAdd(&g_loss_l, (double)s_ll);
        if (s_plc != 0.0f) atomicAdd(&g_loss_c, (double)s_plc);
    }
}

// ---------------- kernel E: per-batch exact top-k sum (hard negative mining) ----------------
__global__ void k_topk() {
    extern __shared__ unsigned sv[];        // NP uints (mined as bits, all >= 0)
    const int n   = blockIdx.x;
    const int tid = threadIdx.x;
    const int nt  = blockDim.x;

    for (int i = tid; i < NP; i += nt)
        sv[i] = __float_as_uint(g_mined[n * NP + i]);

    __shared__ int s_red;
    __shared__ float s_fred;
    __syncthreads();

    const int k = min(3 * g_num_pos[n], NP - 1);

    // binary search: largest u with count(v >= u) >= k   (u* = k-th largest value bits)
    unsigned lo = 0u, hi = 0xFFFFFFFFu;
    while (hi - lo > 1u) {
        unsigned mid = lo + (hi - lo) / 2u;
        int c = 0;
        for (int i = tid; i < NP; i += nt) c += (sv[i] >= mid);
#pragma unroll
        for (int o = 16; o; o >>= 1) c += __shfl_down_sync(0xFFFFFFFFu, c, o);
        __syncthreads();
        if (tid == 0) s_red = 0;
        __syncthreads();
        if ((tid & 31) == 0) atomicAdd(&s_red, c);
        __syncthreads();
        if (s_red >= k) lo = mid; else hi = mid;
    }
    const unsigned u = lo;

    // sum of strictly-greater values + fill remaining slots with the k-th value
    int   cgt = 0;
    float sum = 0.0f;
    for (int i = tid; i < NP; i += nt) {
        unsigned v = sv[i];
        if (v > u) { cgt++; sum += __uint_as_float(v); }
    }
#pragma unroll
    for (int o = 16; o; o >>= 1) {
        cgt += __shfl_down_sync(0xFFFFFFFFu, cgt, o);
        sum += __shfl_down_sync(0xFFFFFFFFu, sum, o);
    }
    __syncthreads();
    if (tid == 0) { s_red = 0; s_fred = 0.0f; }
    __syncthreads();
    if ((tid & 31) == 0) { atomicAdd(&s_red, cgt); atomicAdd(&s_fred, sum); }
    __syncthreads();
    if (tid == 0) {
        float S = s_fred + (float)(k - s_red) * __uint_as_float(u);
        atomicAdd(&g_loss_c, (double)S);
    }
}

// ---------------- kernel F: finalize ----------------
__global__ void k_final(float* out, int out_size) {
    if (threadIdx.x == 0 && blockIdx.x == 0) {
        int ntot = 0;
        for (int i = 0; i < NB; i++) ntot += g_num_pos[i];
        float nf = (float)ntot;
        out[0] = (float)(g_loss_l / (double)nf);
        if (out_size > 1) out[1] = (float)(g_loss_c / (double)nf);
    }
}

// ---------------- launch ----------------
extern "C" void kernel_launch(void* const* d_in, const int* in_sizes, int n_in,
                              void* d_out, int out_size) {
    const float* loc     = (const float*)d_in[0];
    const float* conf    = (const float*)d_in[1];
    const float* priors  = (const float*)d_in[2];
    const float* targets = (const float*)d_in[3];
    float* out = (float*)d_out;

    static bool attr_set = false;
    if (!attr_set) {
        cudaFuncSetAttribute(k_topk, cudaFuncAttributeMaxDynamicSharedMemorySize,
                             NP * (int)sizeof(unsigned));
        attr_set = true;
    }

    dim3 grid((NP + 255) / 256, NB);

    k_init<<<(NB * NM + 255) / 256, 256>>>();
    k_match<<<grid, 256>>>(priors, targets);
    k_force<<<1, NB>>>();
    k_main<<<grid, 256>>>(loc, conf, priors, targets);
    k_topk<<<NB, 1024, NP * sizeof(unsigned)>>>();
    k_final<<<1, 32>>>(out, out_size);
}

// round 6
// speedup vs baseline: 1.1054x; 1.1054x over previous
#include <cuda_runtime.h>
#include <cuda_bf16.h>
#include <math.h>

#define NB 64
#define NP 24564
#define NM 16
#define NC 21
#define TPB 256

// ---------------- device scratch ----------------
__device__ unsigned long long g_winner[NB * NM];   // packed (iou_bits<<32)|(~prior)
__device__ unsigned short     g_code[NB * NP];     // (best_t<<8) | conf_t
__device__ float              g_mined[NB * NP];    // mined conf loss (0 at positives)
__device__ int                g_num_pos[NB];
__device__ double             g_loss_l;
__device__ double             g_loss_c;

// ---------------- kernel A: init ----------------
__global__ void k_init() {
    int i = blockIdx.x * blockDim.x + threadIdx.x;
    if (i < NB * NM) g_winner[i] = 0ull;
    if (i < NB) g_num_pos[i] = 0;
    if (i == 0) { g_loss_l = 0.0; g_loss_c = 0.0; }
}

// ---------------- kernel B: match (IoU, argmaxes via REDUX) ----------------
__global__ void k_match(const float* __restrict__ priors,
                        const float* __restrict__ targets) {
    const int n   = blockIdx.y;
    const int tid = threadIdx.x;

    __shared__ float t_x1[NM], t_y1[NM], t_x2[NM], t_y2[NM], t_area[NM], t_lab[NM];
    __shared__ unsigned long long sh_key[NM];
    if (tid < NM) {
        const float* tp = targets + (size_t)(n * NM + tid) * 5;
        float x1 = tp[0], y1 = tp[1], x2 = tp[2], y2 = tp[3];
        t_x1[tid] = x1; t_y1[tid] = y1; t_x2[tid] = x2; t_y2[tid] = y2;
        t_area[tid] = (x2 - x1) * (y2 - y1);
        t_lab[tid] = tp[4];
        sh_key[tid] = 0ull;
    }
    __syncthreads();

    const int p = blockIdx.x * blockDim.x + tid;
    const bool valid = p < NP;
    const int lane = tid & 31;

    float px1 = 0.f, py1 = 0.f, px2 = 0.f, py2 = 0.f, pa = 1.f;
    if (valid) {
        float4 pr = ((const float4*)priors)[p];
        px1 = pr.x - pr.z * 0.5f; py1 = pr.y - pr.w * 0.5f;
        px2 = pr.x + pr.z * 0.5f; py2 = pr.y + pr.w * 0.5f;
        pa  = (px2 - px1) * (py2 - py1);
    }

    float best_ov = -1.0f; int best_t = 0;
#pragma unroll
    for (int t = 0; t < NM; t++) {
        float iou = 0.0f;
        if (valid) {
            float ix = fmaxf(fminf(px2, t_x2[t]) - fmaxf(px1, t_x1[t]), 0.0f);
            float iy = fmaxf(fminf(py2, t_y2[t]) - fmaxf(py1, t_y1[t]), 0.0f);
            float inter = ix * iy;
            iou = inter / (pa + t_area[t] - inter);     // IEEE div: bit-match reference
            if (iou > best_ov) { best_ov = iou; best_t = t; }   // first-index tiebreak
        }
        // per-truth warp argmax: HW REDUX on float bits (iou >= 0)
        unsigned b    = __float_as_uint(iou);
        unsigned wmax = __reduce_max_sync(0xFFFFFFFFu, b);
        unsigned ball = __ballot_sync(0xFFFFFFFFu, b == wmax);
        if (valid && lane == (__ffs(ball) - 1)) {       // lowest lane = lowest p
            atomicMax(&sh_key[t],
                      ((unsigned long long)wmax << 32) |
                      (unsigned long long)(0xFFFFFFFFu - (unsigned)p));
        }
    }

    if (valid) {
        int conf_t = (best_ov < 0.5f) ? 0 : ((int)t_lab[best_t] + 1);
        g_code[(size_t)n * NP + p] = (unsigned short)((best_t << 8) | conf_t);
    }
    __syncthreads();
    if (tid < NM && sh_key[tid])
        atomicMax(&g_winner[n * NM + tid], sh_key[tid]);
}

// ---------------- kernel C: forced-match overrides (last truth wins) ----------------
__global__ void k_force(const float* __restrict__ targets) {
    int n = threadIdx.x;
    if (n >= NB) return;
    for (int t = 0; t < NM; t++) {                 // sequential: last write wins
        unsigned long long w = g_winner[n * NM + t];
        unsigned p = 0xFFFFFFFFu - (unsigned)(w & 0xFFFFFFFFull);
        int lab = (int)targets[(size_t)(n * NM + t) * 5 + 4];
        g_code[(size_t)n * NP + p] = (unsigned short)((t << 8) | (lab + 1));  // ov=2 -> pos
    }
}

__device__ __forceinline__ float sl1(float d) {
    float a = fabsf(d);
    return (a < 1.0f) ? 0.5f * d * d : a - 0.5f;
}

// ---------------- kernel D: LSE + gather + smooth-L1 + mined (SMEM-staged conf) ----------------
__global__ void k_main(const float* __restrict__ loc,
                       const float* __restrict__ conf,
                       const float* __restrict__ priors,
                       const float* __restrict__ targets) {
    const int n   = blockIdx.y;
    const int tid = threadIdx.x;
    const int rb  = blockIdx.x * TPB;

    __shared__ float t_x1[NM], t_y1[NM], t_x2[NM], t_y2[NM];
    __shared__ float sbuf[TPB * NC];           // 21504 B conf staging
    __shared__ float s_ll, s_plc; __shared__ int s_np;

    if (tid < NM) {
        const float* tp = targets + (size_t)(n * NM + tid) * 5;
        t_x1[tid] = tp[0]; t_y1[tid] = tp[1];
        t_x2[tid] = tp[2]; t_y2[tid] = tp[3];
    }
    if (tid == 0) { s_ll = 0.0f; s_plc = 0.0f; s_np = 0; }

    // stage conf rows [rb, rb+rows) via coalesced float4 (rows*21 always %4==0 here)
    const int rows = min(TPB, NP - rb);
    const int nf4  = rows * NC / 4;
    const float4* src = (const float4*)(conf + ((size_t)n * NP + rb) * NC);
    float4* dst = (float4*)sbuf;
    for (int i = tid; i < nf4; i += TPB) dst[i] = src[i];
    __syncthreads();

    float local_ll = 0.0f, local_plc = 0.0f;
    int   local_np = 0;

    if (tid < rows) {
        const int p = rb + tid;
        unsigned code = g_code[(size_t)n * NP + p];
        int conf_t = code & 255;
        int bt     = code >> 8;
        bool pos   = conf_t > 0;

        const float* v = sbuf + tid * NC;      // stride 21: bank-conflict-free
        float mx = v[0];
#pragma unroll
        for (int c = 1; c < NC; c++) mx = fmaxf(mx, v[c]);
        float s = 0.0f;
#pragma unroll
        for (int c = 0; c < NC; c++) s += __expf(v[c] - mx);
        float lse = mx + __logf(s);
        float lc  = lse - v[conf_t];

        g_mined[(size_t)n * NP + p] = pos ? 0.0f : lc;

        if (pos) {
            local_np  = 1;
            local_plc = lc;
            float4 pr = ((const float4*)priors)[p];
            float mx1 = t_x1[bt], my1 = t_y1[bt], mx2 = t_x2[bt], my2 = t_y2[bt];
            float gx = ((mx1 + mx2) * 0.5f - pr.x) / (0.1f * pr.z);
            float gy = ((my1 + my2) * 0.5f - pr.y) / (0.1f * pr.w);
            float gw = logf((mx2 - mx1) / pr.z) / 0.2f;
            float gh = logf((my2 - my1) / pr.w) / 0.2f;
            const float* lp = loc + ((size_t)n * NP + (size_t)p) * 4;
            local_ll = sl1(lp[0] - gx) + sl1(lp[1] - gy)
                     + sl1(lp[2] - gw) + sl1(lp[3] - gh);
        }
    }

#pragma unroll
    for (int o = 16; o; o >>= 1) {
        local_ll  += __shfl_down_sync(0xFFFFFFFFu, local_ll,  o);
        local_plc += __shfl_down_sync(0xFFFFFFFFu, local_plc, o);
        local_np  += __shfl_down_sync(0xFFFFFFFFu, local_np,  o);
    }
    __syncthreads();
    if ((tid & 31) == 0) {
        if (local_ll  != 0.0f) atomicAdd(&s_ll,  local_ll);
        if (local_plc != 0.0f) atomicAdd(&s_plc, local_plc);
        if (local_np)          atomicAdd(&s_np,  local_np);
    }
    __syncthreads();
    if (tid == 0) {
        if (s_np)          atomicAdd(&g_num_pos[n], s_np);
        if (s_ll  != 0.0f) atomicAdd(&g_loss_l, (double)s_ll);
        if (s_plc != 0.0f) atomicAdd(&g_loss_c, (double)s_plc);
    }
}

// ---------------- kernel E: per-batch top-k sum via 8-bit radix select ----------------
// NOTE: every loop containing __ballot_sync/__match_any_sync runs a UNIFORM
// trip count (padded bound + in-bounds predicate) so no warp is ever split.
__global__ void k_topk() {
    extern __shared__ unsigned sv[];        // NP uints (loss bits, all >= 0)
    __shared__ int hist[256];
    __shared__ unsigned s_b; __shared__ int s_acc;
    __shared__ int s_ci; __shared__ float s_cs;

    const int n   = blockIdx.x;
    const int tid = threadIdx.x;
    const int nt  = blockDim.x;                          // 1024
    const int NP_PAD = ((NP + 1023) / 1024) * 1024;      // 24576

    const uint4* src = (const uint4*)(g_mined + (size_t)n * NP);   // NP % 4 == 0
    uint4* dstv = (uint4*)sv;
    for (int i = tid; i < NP / 4; i += nt) dstv[i] = src[i];

    const int k = min(3 * g_num_pos[n], NP - 1);
    __syncthreads();
    if (k <= 0) return;

    unsigned prefix = 0;
    int kr = k;
#pragma unroll
    for (int shift = 24; shift >= 0; shift -= 8) {
        if (tid < 256) hist[tid] = 0;
        __syncthreads();
        for (int i = tid; i < NP_PAD; i += nt) {         // uniform trip count
            const bool inb = i < NP;
            unsigned v = inb ? sv[i] : 0u;
            bool m = inb && ((shift == 24) || ((v >> (shift + 8)) == prefix));
            unsigned active = __ballot_sync(0xFFFFFFFFu, m);
            if (m) {
                unsigned bin = (v >> shift) & 255u;
                unsigned peers = __match_any_sync(active, bin);  // warp-aggregate
                if ((tid & 31) == (__ffs(peers) - 1))
                    atomicAdd(&hist[bin], __popc(peers));
            }
        }
        __syncthreads();
        if (tid == 0) {
            int acc = 0; int b = 255;
            for (; b > 0; b--) { if (acc + hist[b] >= kr) break; acc += hist[b]; }
            s_b = (unsigned)b; s_acc = acc;
        }
        __syncthreads();
        prefix = (prefix << 8) | s_b;
        kr -= s_acc;
    }

    // sum strictly-greater + fill remaining slots with the k-th value
    const unsigned u = prefix;
    int   cgt = 0;
    float sum = 0.0f;
    for (int i = tid; i < NP; i += nt) {                 // no sync intrinsics inside
        unsigned v = sv[i];
        if (v > u) { cgt++; sum += __uint_as_float(v); }
    }
#pragma unroll
    for (int o = 16; o; o >>= 1) {
        cgt += __shfl_down_sync(0xFFFFFFFFu, cgt, o);
        sum += __shfl_down_sync(0xFFFFFFFFu, sum, o);
    }
    if (tid == 0) { s_ci = 0; s_cs = 0.0f; }
    __syncthreads();
    if ((tid & 31) == 0) { atomicAdd(&s_ci, cgt); atomicAdd(&s_cs, sum); }
    __syncthreads();
    if (tid == 0) {
        float S = s_cs + (float)(k - s_ci) * __uint_as_float(u);
        atomicAdd(&g_loss_c, (double)S);
    }
}

// ---------------- kernel F: finalize ----------------
__global__ void k_final(float* out, int out_size) {
    if (threadIdx.x == 0 && blockIdx.x == 0) {
        int ntot = 0;
        for (int i = 0; i < NB; i++) ntot += g_num_pos[i];
        float nf = (float)ntot;
        out[0] = (float)(g_loss_l / (double)nf);
        if (out_size > 1) out[1] = (float)(g_loss_c / (double)nf);
    }
}

// ---------------- launch ----------------
extern "C" void kernel_launch(void* const* d_in, const int* in_sizes, int n_in,
                              void* d_out, int out_size) {
    const float* loc     = (const float*)d_in[0];
    const float* conf    = (const float*)d_in[1];
    const float* priors  = (const float*)d_in[2];
    const float* targets = (const float*)d_in[3];
    float* out = (float*)d_out;

    static bool attr_set = false;
    if (!attr_set) {
        cudaFuncSetAttribute(k_topk, cudaFuncAttributeMaxDynamicSharedMemorySize,
                             NP * (int)sizeof(unsigned));
        attr_set = true;
    }

    dim3 grid((NP + TPB - 1) / TPB, NB);

    k_init<<<(NB * NM + 255) / 256, 256>>>();
    k_match<<<grid, TPB>>>(priors, targets);
    k_force<<<1, NB>>>(targets);
    k_main<<<grid, TPB>>>(loc, conf, priors, targets);
    k_topk<<<NB, 1024, NP * sizeof(unsigned)>>>();
    k_final<<<1, 32>>>(out, out_size);
}